// round 4
// baseline (speedup 1.0000x reference)
#include <cuda_runtime.h>
#include <math.h>

#define Bv 16
#define Tv 512
#define Sv 2048
#define Dv 768
#define SC 16            // s-chunks in context pass
#define TCH 16           // t-rows per output block
#define ABLK 128         // score blocks per batch

// Scratch (__device__ globals: allocation-free rule)
__device__ float g_score[Bv * Sv];
__device__ float g_weight[Bv * Sv];
__device__ float g_pctx[Bv * SC * Dv];
__device__ float g_ctx[Bv * Dv];
__device__ float g_cg[Bv];
__device__ int   g_cntA[Bv];   // zero-init; self-resetting
__device__ int   g_cntC[Bv];   // zero-init; self-resetting

// ---------------------------------------------------------------------------
// A: enc_score rows + fused per-batch softmax (last block per batch).
// grid = (ABLK, B), 256 threads. Each block: 16 rows (8 warps x 2 rows).
// ---------------------------------------------------------------------------
__global__ void k_score_softmax(const float* __restrict__ enc,
                                const int* __restrict__ mask,
                                const float* __restrict__ w_ptr) {
    int b = blockIdx.y;
    int tid = threadIdx.x;
    int warp = tid >> 5, lane = tid & 31;
    const float4* w = reinterpret_cast<const float4*>(w_ptr + Dv);

#pragma unroll
    for (int k = 0; k < 2; k++) {
        int s = blockIdx.x * 16 + warp * 2 + k;
        size_t bs = (size_t)b * Sv + s;
        const float4* row = reinterpret_cast<const float4*>(enc) + bs * (Dv / 4);
        float acc = 0.f;
#pragma unroll
        for (int i = 0; i < 6; i++) {
            float4 a  = row[lane + 32 * i];
            float4 ww = __ldg(&w[lane + 32 * i]);
            acc += a.x * ww.x + a.y * ww.y + a.z * ww.z + a.w * ww.w;
        }
#pragma unroll
        for (int o = 16; o; o >>= 1) acc += __shfl_xor_sync(0xffffffffu, acc, o);
        if (lane == 0) g_score[bs] = mask[bs] ? acc : -1e9f;
    }

    // last-block-per-batch softmax
    __threadfence();
    __shared__ int isLast;
    if (tid == 0) {
        int v = atomicAdd(&g_cntA[b], 1);
        isLast = (v == ABLK - 1);
        if (isLast) g_cntA[b] = 0;               // reset for next replay
    }
    __syncthreads();
    if (!isLast) return;

    float v[8];
    float m = -3e38f;
#pragma unroll
    for (int i = 0; i < 8; i++) {
        v[i] = g_score[(size_t)b * Sv + tid + 256 * i];
        m = fmaxf(m, v[i]);
    }
    __shared__ float redm[8], reds[8];
#pragma unroll
    for (int o = 16; o; o >>= 1) m = fmaxf(m, __shfl_xor_sync(0xffffffffu, m, o));
    if (lane == 0) redm[warp] = m;
    __syncthreads();
    m = redm[0];
#pragma unroll
    for (int i = 1; i < 8; i++) m = fmaxf(m, redm[i]);

    float s = 0.f;
#pragma unroll
    for (int i = 0; i < 8; i++) { v[i] = expf(v[i] - m); s += v[i]; }
#pragma unroll
    for (int o = 16; o; o >>= 1) s += __shfl_xor_sync(0xffffffffu, s, o);
    if (lane == 0) reds[warp] = s;
    __syncthreads();
    s = reds[0];
#pragma unroll
    for (int i = 1; i < 8; i++) s += reds[i];
    float inv = 1.f / s;
#pragma unroll
    for (int i = 0; i < 8; i++)
        g_weight[(size_t)b * Sv + tid + 256 * i] = v[i] * inv;
}

// ---------------------------------------------------------------------------
// C: partial context + fused reduce (last block per batch).
// grid = (SC, B), 192 threads (each owns 4 consecutive d's via float4).
// ---------------------------------------------------------------------------
__global__ void k_ctx(const float* __restrict__ enc,
                      const float* __restrict__ w_gen) {
    int sc = blockIdx.x, b = blockIdx.y;
    int tid = threadIdx.x;                                // 0..191
    int warp = tid >> 5, lane = tid & 31;

    __shared__ float w[Sv / SC];                          // 128
    if (tid < Sv / SC) w[tid] = g_weight[(size_t)b * Sv + sc * (Sv / SC) + tid];
    __syncthreads();

    const float4* e = reinterpret_cast<const float4*>(enc)
                    + ((size_t)b * Sv + (size_t)sc * (Sv / SC)) * (Dv / 4) + tid;
    float4 acc = make_float4(0.f, 0.f, 0.f, 0.f);
#pragma unroll 8
    for (int s = 0; s < Sv / SC; s++) {
        float ws = w[s];
        float4 v = e[(size_t)s * (Dv / 4)];
        acc.x += ws * v.x; acc.y += ws * v.y;
        acc.z += ws * v.z; acc.w += ws * v.w;
    }
    reinterpret_cast<float4*>(g_pctx)[(size_t)(b * SC + sc) * (Dv / 4) + tid] = acc;

    // last-block-per-batch: reduce SC partials -> ctx, cg
    __threadfence();
    __shared__ int isLast;
    if (tid == 0) {
        int v = atomicAdd(&g_cntC[b], 1);
        isLast = (v == SC - 1);
        if (isLast) g_cntC[b] = 0;
    }
    __syncthreads();
    if (!isLast) return;

    const float4* p4 = reinterpret_cast<const float4*>(g_pctx) + (size_t)b * SC * (Dv / 4);
    float4 c = make_float4(0.f, 0.f, 0.f, 0.f);
#pragma unroll
    for (int p = 0; p < SC; p++) {
        float4 v = p4[(size_t)p * (Dv / 4) + tid];
        c.x += v.x; c.y += v.y; c.z += v.z; c.w += v.w;
    }
    reinterpret_cast<float4*>(g_ctx)[(size_t)b * (Dv / 4) + tid] = c;

    float4 g = __ldg(reinterpret_cast<const float4*>(w_gen + Dv) + tid);
    float dot = c.x * g.x + c.y * g.y + c.z * g.z + c.w * g.w;
    __shared__ float red[6];
#pragma unroll
    for (int o = 16; o; o >>= 1) dot += __shfl_xor_sync(0xffffffffu, dot, o);
    if (lane == 0) red[warp] = dot;
    __syncthreads();
    if (tid == 0) {
        float s = red[0] + red[1] + red[2] + red[3] + red[4] + red[5];
        g_cg[b] = s;
    }
}

// ---------------------------------------------------------------------------
// F: one block per (b, 16-t chunk). Smem-staged broadcast rows, streaming
// stores; p_gen via per-warp dec dots.
// Output layout: [pw (B*T*S)] [p_gen (B*T)] [context (B*T*D)]
// ---------------------------------------------------------------------------
__global__ void k_out(const float* __restrict__ dec,
                      const float* __restrict__ w_gen,
                      const float* __restrict__ b_gen,
                      float* __restrict__ out) {
    int b = blockIdx.y;
    int t0 = blockIdx.x * TCH;
    int tid = threadIdx.x;                                // 256 threads
    int warp = tid >> 5, lane = tid & 31;

    __shared__ float sw[Sv];
    __shared__ float sc[Dv];
    __shared__ float spg[TCH];

    float4* sw4 = reinterpret_cast<float4*>(sw);
    const float4* gw4 = reinterpret_cast<const float4*>(g_weight) + (size_t)b * (Sv / 4);
#pragma unroll
    for (int i = 0; i < 2; i++) sw4[tid + 256 * i] = gw4[tid + 256 * i];
    float4* sc4 = reinterpret_cast<float4*>(sc);
    const float4* gc4 = reinterpret_cast<const float4*>(g_ctx) + (size_t)b * (Dv / 4);
    if (tid < Dv / 4) sc4[tid] = gc4[tid];

#pragma unroll
    for (int k = 0; k < 2; k++) {
        int tt = warp * 2 + k;
        size_t bt = (size_t)b * Tv + t0 + tt;
        const float4* drow = reinterpret_cast<const float4*>(dec) + bt * (Dv / 4);
        const float4* g4   = reinterpret_cast<const float4*>(w_gen);
        float acc = 0.f;
#pragma unroll
        for (int i = 0; i < 6; i++) {
            float4 a = __ldcs(&drow[lane + 32 * i]);
            float4 g = __ldg(&g4[lane + 32 * i]);
            acc += a.x * g.x + a.y * g.y + a.z * g.z + a.w * g.w;
        }
#pragma unroll
        for (int o = 16; o; o >>= 1) acc += __shfl_xor_sync(0xffffffffu, acc, o);
        if (lane == 0) spg[tt] = acc;
    }
    __syncthreads();

    float* ctx_base = out + (size_t)Bv * Tv * Sv + (size_t)Bv * Tv;
#pragma unroll 4
    for (int tt = 0; tt < TCH; tt++) {
        size_t bt = (size_t)b * Tv + t0 + tt;
        float4* pw4 = reinterpret_cast<float4*>(out) + bt * (Sv / 4);
#pragma unroll
        for (int i = 0; i < 2; i++)
            __stcs(&pw4[tid + 256 * i], sw4[tid + 256 * i]);
        if (tid < Dv / 4) {
            float4* c4 = reinterpret_cast<float4*>(ctx_base) + bt * (Dv / 4);
            __stcs(&c4[tid], sc4[tid]);
        }
    }

    if (tid < TCH) {
        float x = spg[tid] + g_cg[b] + __ldg(&b_gen[0]);
        out[(size_t)Bv * Tv * Sv + (size_t)b * Tv + t0 + tid] = 1.f / (1.f + expf(-x));
    }
}

// ---------------------------------------------------------------------------
extern "C" void kernel_launch(void* const* d_in, const int* in_sizes, int n_in,
                              void* d_out, int out_size) {
    const float* dec    = (const float*)d_in[0];
    const float* enc    = (const float*)d_in[1];
    const int*   mask   = (const int*)d_in[2];
    const float* w_ptr  = (const float*)d_in[3];
    // d_in[4] = b_ptr (zeros; cancels in softmax)
    const float* w_gen  = (const float*)d_in[5];
    const float* b_gen  = (const float*)d_in[6];
    float* out = (float*)d_out;

    dim3 ga(ABLK, Bv);
    k_score_softmax<<<ga, 256>>>(enc, mask, w_ptr);
    dim3 gc(SC, Bv);
    k_ctx<<<gc, 192>>>(enc, w_gen);
    dim3 gf(Tv / TCH, Bv);
    k_out<<<gf, 256>>>(dec, w_gen, b_gen, out);
}

// round 5
// speedup vs baseline: 1.2605x; 1.2605x over previous
#include <cuda_runtime.h>
#include <math.h>

#define Bv 16
#define Tv 512
#define Sv 2048
#define Dv 768
#define SCH 64           // s-chunks per batch (fused pass)
#define RPB 32           // s-rows per block (Sv/SCH)
#define TCH 16           // t-rows per output block

// Scratch (__device__ globals: allocation-free rule)
__device__ float g_score[Bv * Sv];
__device__ float g_pctx[Bv * SCH * Dv];     // 3 MB
__device__ float g_pmax[Bv * SCH];
__device__ float g_psum[Bv * SCH];
__device__ float g_ctx[Bv * Dv];
__device__ float g_cg[Bv];
__device__ float g_M[Bv];
__device__ float g_inv[Bv];

// ---------------------------------------------------------------------------
// K1: fused score + online-softmax partial context. grid=(SCH,B), 256 thr.
// Phase 1: 8 warps x 4 rows -> masked scores (smem + g_score), chunk max/sum.
// Phase 2: 192 threads (float4 over D) accumulate exp-weighted enc rows,
//          re-reading the block's 96KB of enc from L1.
// ---------------------------------------------------------------------------
__global__ void __launch_bounds__(256, 2)
k_score_ctx(const float* __restrict__ enc,
            const int* __restrict__ mask,
            const float* __restrict__ w_ptr) {
    int b = blockIdx.y, ch = blockIdx.x;
    int tid = threadIdx.x;
    int warp = tid >> 5, lane = tid & 31;

    __shared__ float ss[RPB];      // raw masked scores
    __shared__ float se[RPB];      // exp(score - lmax)

    const float4* w4 = reinterpret_cast<const float4*>(w_ptr + Dv);
    const float4* enc4 = reinterpret_cast<const float4*>(enc);

    // ---- phase 1: scores, 2 rows interleaved for MLP ----
#pragma unroll
    for (int rp = 0; rp < 2; rp++) {
        int r = warp * 4 + rp * 2;
        size_t bs = (size_t)b * Sv + ch * RPB + r;
        const float4* row0 = enc4 + bs * (Dv / 4);
        const float4* row1 = row0 + (Dv / 4);
        float a0 = 0.f, a1 = 0.f;
#pragma unroll
        for (int i = 0; i < 6; i++) {
            float4 x0 = row0[lane + 32 * i];
            float4 x1 = row1[lane + 32 * i];
            float4 ww = __ldg(&w4[lane + 32 * i]);
            a0 += x0.x * ww.x + x0.y * ww.y + x0.z * ww.z + x0.w * ww.w;
            a1 += x1.x * ww.x + x1.y * ww.y + x1.z * ww.z + x1.w * ww.w;
        }
#pragma unroll
        for (int o = 16; o; o >>= 1) {
            a0 += __shfl_xor_sync(0xffffffffu, a0, o);
            a1 += __shfl_xor_sync(0xffffffffu, a1, o);
        }
        if (lane == 0) {
            float m0 = mask[bs]     ? a0 : -1e9f;
            float m1 = mask[bs + 1] ? a1 : -1e9f;
            ss[r] = m0; ss[r + 1] = m1;
            g_score[bs] = m0; g_score[bs + 1] = m1;
        }
    }
    __syncthreads();

    // ---- chunk-local max / exp / sum (warp 0 over 32 rows) ----
    if (tid < 32) {
        float v = ss[tid];
        float m = v;
#pragma unroll
        for (int o = 16; o; o >>= 1) m = fmaxf(m, __shfl_xor_sync(0xffffffffu, m, o));
        float e = expf(v - m);
        se[tid] = e;
        float s = e;
#pragma unroll
        for (int o = 16; o; o >>= 1) s += __shfl_xor_sync(0xffffffffu, s, o);
        if (tid == 0) {
            g_pmax[b * SCH + ch] = m;
            g_psum[b * SCH + ch] = s;
        }
    }
    __syncthreads();

    // ---- phase 2: partial ctx (enc rows hot in L1) ----
    if (tid < Dv / 4) {
        const float4* e4 = enc4 + ((size_t)b * Sv + ch * RPB) * (Dv / 4) + tid;
        float4 acc = make_float4(0.f, 0.f, 0.f, 0.f);
#pragma unroll 8
        for (int s = 0; s < RPB; s++) {
            float ws = se[s];
            float4 v = e4[(size_t)s * (Dv / 4)];
            acc.x += ws * v.x; acc.y += ws * v.y;
            acc.z += ws * v.z; acc.w += ws * v.w;
        }
        reinterpret_cast<float4*>(g_pctx)[(size_t)(b * SCH + ch) * (Dv / 4) + tid] = acc;
    }
}

// ---------------------------------------------------------------------------
// K2: per-batch combine of SCH chunks with softmax rescale.
// grid=B, 192 threads. Outputs g_ctx, g_cg, g_M, g_inv.
// ---------------------------------------------------------------------------
__global__ void k_reduce(const float* __restrict__ w_gen) {
    int b = blockIdx.x, tid = threadIdx.x;
    int warp = tid >> 5, lane = tid & 31;

    __shared__ float sf[SCH];
    __shared__ float smax, sS;
    __shared__ float r2[2], red[6];

    // global max over 64 chunk maxima
    if (tid < 32) {
        float m = fmaxf(g_pmax[b * SCH + tid], g_pmax[b * SCH + tid + 32]);
#pragma unroll
        for (int o = 16; o; o >>= 1) m = fmaxf(m, __shfl_xor_sync(0xffffffffu, m, o));
        if (tid == 0) smax = m;
    }
    __syncthreads();
    float M = smax;

    // scale factors + global sum
    if (tid < 64) {
        float f = expf(g_pmax[b * SCH + tid] - M);
        sf[tid] = f;
        float c = f * g_psum[b * SCH + tid];
#pragma unroll
        for (int o = 16; o; o >>= 1) c += __shfl_xor_sync(0xffffffffu, c, o);
        if (lane == 0) r2[warp] = c;
    }
    __syncthreads();
    if (tid == 0) sS = r2[0] + r2[1];
    __syncthreads();
    float inv = 1.f / sS;

    // ctx = (sum_c f_c * pctx_c) * inv
    const float4* p4 = reinterpret_cast<const float4*>(g_pctx) + (size_t)b * SCH * (Dv / 4);
    float4 acc = make_float4(0.f, 0.f, 0.f, 0.f);
#pragma unroll 8
    for (int c = 0; c < SCH; c++) {
        float f = sf[c];
        float4 v = p4[(size_t)c * (Dv / 4) + tid];
        acc.x += f * v.x; acc.y += f * v.y;
        acc.z += f * v.z; acc.w += f * v.w;
    }
    acc.x *= inv; acc.y *= inv; acc.z *= inv; acc.w *= inv;
    reinterpret_cast<float4*>(g_ctx)[(size_t)b * (Dv / 4) + tid] = acc;

    // cg = ctx . w_gen[D:2D]
    float4 g = __ldg(reinterpret_cast<const float4*>(w_gen + Dv) + tid);
    float dot = acc.x * g.x + acc.y * g.y + acc.z * g.z + acc.w * g.w;
#pragma unroll
    for (int o = 16; o; o >>= 1) dot += __shfl_xor_sync(0xffffffffu, dot, o);
    if (lane == 0) red[warp] = dot;
    __syncthreads();
    if (tid == 0) {
        g_cg[b] = red[0] + red[1] + red[2] + red[3] + red[4] + red[5];
        g_M[b] = M;
        g_inv[b] = inv;
    }
}

// ---------------------------------------------------------------------------
// F: one block per (b, 16-t chunk). Normalize weights on the fly while
// staging into smem; broadcast via streaming stores; p_gen per-warp dots.
// Output layout: [pw (B*T*S)] [p_gen (B*T)] [context (B*T*D)]
// ---------------------------------------------------------------------------
__global__ void k_out(const float* __restrict__ dec,
                      const float* __restrict__ w_gen,
                      const float* __restrict__ b_gen,
                      float* __restrict__ out) {
    int b = blockIdx.y;
    int t0 = blockIdx.x * TCH;
    int tid = threadIdx.x;                                // 256 threads
    int warp = tid >> 5, lane = tid & 31;

    __shared__ float sw[Sv];
    __shared__ float sc[Dv];
    __shared__ float spg[TCH];

    float M = g_M[b], inv = g_inv[b];
    float4* sw4 = reinterpret_cast<float4*>(sw);
    const float4* gs4 = reinterpret_cast<const float4*>(g_score) + (size_t)b * (Sv / 4);
#pragma unroll
    for (int i = 0; i < 2; i++) {
        float4 v = gs4[tid + 256 * i];
        float4 wv;
        wv.x = expf(v.x - M) * inv;
        wv.y = expf(v.y - M) * inv;
        wv.z = expf(v.z - M) * inv;
        wv.w = expf(v.w - M) * inv;
        sw4[tid + 256 * i] = wv;
    }
    float4* sc4 = reinterpret_cast<float4*>(sc);
    const float4* gc4 = reinterpret_cast<const float4*>(g_ctx) + (size_t)b * (Dv / 4);
    if (tid < Dv / 4) sc4[tid] = gc4[tid];

#pragma unroll
    for (int k = 0; k < 2; k++) {
        int tt = warp * 2 + k;
        size_t bt = (size_t)b * Tv + t0 + tt;
        const float4* drow = reinterpret_cast<const float4*>(dec) + bt * (Dv / 4);
        const float4* g4   = reinterpret_cast<const float4*>(w_gen);
        float acc = 0.f;
#pragma unroll
        for (int i = 0; i < 6; i++) {
            float4 a = __ldcs(&drow[lane + 32 * i]);
            float4 g = __ldg(&g4[lane + 32 * i]);
            acc += a.x * g.x + a.y * g.y + a.z * g.z + a.w * g.w;
        }
#pragma unroll
        for (int o = 16; o; o >>= 1) acc += __shfl_xor_sync(0xffffffffu, acc, o);
        if (lane == 0) spg[tt] = acc;
    }
    __syncthreads();

    float* ctx_base = out + (size_t)Bv * Tv * Sv + (size_t)Bv * Tv;
#pragma unroll 4
    for (int tt = 0; tt < TCH; tt++) {
        size_t bt = (size_t)b * Tv + t0 + tt;
        float4* pw4 = reinterpret_cast<float4*>(out) + bt * (Sv / 4);
#pragma unroll
        for (int i = 0; i < 2; i++)
            __stcs(&pw4[tid + 256 * i], sw4[tid + 256 * i]);
        if (tid < Dv / 4) {
            float4* c4 = reinterpret_cast<float4*>(ctx_base) + bt * (Dv / 4);
            __stcs(&c4[tid], sc4[tid]);
        }
    }

    if (tid < TCH) {
        float x = spg[tid] + g_cg[b] + __ldg(&b_gen[0]);
        out[(size_t)Bv * Tv * Sv + (size_t)b * Tv + t0 + tid] = 1.f / (1.f + expf(-x));
    }
}

// ---------------------------------------------------------------------------
extern "C" void kernel_launch(void* const* d_in, const int* in_sizes, int n_in,
                              void* d_out, int out_size) {
    const float* dec    = (const float*)d_in[0];
    const float* enc    = (const float*)d_in[1];
    const int*   mask   = (const int*)d_in[2];
    const float* w_ptr  = (const float*)d_in[3];
    // d_in[4] = b_ptr (zeros; cancels in softmax)
    const float* w_gen  = (const float*)d_in[5];
    const float* b_gen  = (const float*)d_in[6];
    float* out = (float*)d_out;

    dim3 g1(SCH, Bv);
    k_score_ctx<<<g1, 256>>>(enc, mask, w_ptr);
    k_reduce<<<Bv, 192>>>(w_gen);
    dim3 gf(Tv / TCH, Bv);
    k_out<<<gf, 256>>>(dec, w_gen, b_gen, out);
}